// round 9
// baseline (speedup 1.0000x reference)
#include <cuda_runtime.h>
#include <cuda_fp16.h>
#include <cstdint>
#include <math.h>

#define BB 128
#define TT 512
#define II 256
#define HH 1024
#define GG 4096
#define CC 1000
#define KTOT 1280
#define NCTA 128
#define NTHR 512
#define NCHUNK_H 8         // h-part K=1024 in 8 chunks of 128

// Persistent kernel SMEM: Whh slice 32x1024 fp16 (2048B rows) + A double buf
#define W_HI 0u
#define A_BUF 65536u
#define ABUF_STRIDE 32768u
#define SMEM_DYN (131072 + 256)

// Precompute kernel SMEM: B 64K | A_hi 64K | A_lo 64K
#define PRE_B  0u
#define PRE_AH 65536u
#define PRE_AL 131072u
#define SMEM_PRE (196608 + 256)

// ---------------- device globals (no dynamic alloc) ---------------------------
__device__ __align__(16) __half g_Wh[GG * KTOT];            // weights fp16, permuted
__device__ __align__(16) __half g_xh[TT * BB * II];         // x hi, [t][m][k]
__device__ __align__(16) __half g_xl[TT * BB * II];         // x lo
__device__ __align__(16) __half g_hh[2][BB * HH];           // h fp16 ping-pong
__device__ float g_c[BB * HH];
__device__ float g_bs[GG];
__device__ float g_xg[268435456];                           // [t][nb][m][32] = 1 GB
__device__ unsigned g_gc[8];                                // per-chunk-group counters

// ---------------- helpers ------------------------------------------------------
__device__ __forceinline__ uint32_t smem_u32(const void* p) {
    uint32_t a;
    asm("{ .reg .u64 t; cvta.to.shared.u64 t, %1; cvt.u32.u64 %0, t; }" : "=r"(a) : "l"(p));
    return a;
}
__device__ __forceinline__ void cp16(uint32_t saddr, const void* gaddr) {
    asm volatile("cp.async.cg.shared.global [%0], [%1], 16;" :: "r"(saddr), "l"(gaddr) : "memory");
}
__device__ __forceinline__ void ldsm4(uint32_t addr, uint32_t& r0, uint32_t& r1,
                                      uint32_t& r2, uint32_t& r3) {
    asm volatile("ldmatrix.sync.aligned.m8n8.x4.shared.b16 {%0,%1,%2,%3}, [%4];"
                 : "=r"(r0), "=r"(r1), "=r"(r2), "=r"(r3) : "r"(addr));
}
__device__ __forceinline__ void mma16816(float* c, const uint32_t* a, uint32_t b0, uint32_t b1) {
    asm volatile(
        "mma.sync.aligned.m16n8k16.row.col.f32.f16.f16.f32 "
        "{%0,%1,%2,%3}, {%4,%5,%6,%7}, {%8,%9}, {%0,%1,%2,%3};"
        : "+f"(c[0]), "+f"(c[1]), "+f"(c[2]), "+f"(c[3])
        : "r"(a[0]), "r"(a[1]), "r"(a[2]), "r"(a[3]), "r"(b0), "r"(b1));
}
__device__ __forceinline__ void gwait(int g, unsigned need) {
    unsigned v;
    do {
        asm volatile("ld.acquire.gpu.global.u32 %0, [%1];"
                     : "=r"(v) : "l"(&g_gc[g]) : "memory");
    } while (v < need);
}

// ---------------- prep kernels -------------------------------------------------
// Stored row r = nb*32 + hc*4 + q  <->  original row q*H + nb*8 + hc.
__global__ void prep_w(const float* __restrict__ Wih, const float* __restrict__ Whh) {
    int idx = blockIdx.x * blockDim.x + threadIdx.x;
    if (idx >= GG * KTOT) return;
    int r = idx / KTOT, k = idx - r * KTOT;
    int nb = r >> 5, j = r & 31, hc = j >> 2, q = j & 3;
    int orig = q * HH + nb * 8 + hc;
    float v = (k < II) ? Wih[(size_t)orig * II + k] : Whh[(size_t)orig * HH + (k - II)];
    g_Wh[idx] = __float2half_rn(v);
}

__global__ void prep_x(const float* __restrict__ x) {
    int idx = blockIdx.x * blockDim.x + threadIdx.x;
    if (idx >= TT * BB * II) return;
    int t = idx / (BB * II);
    int rem = idx - t * (BB * II);
    int m = rem / II, k = rem - m * II;
    float v = x[((size_t)m * TT + t) * II + k];
    __half hi = __float2half_rn(v);
    g_xh[idx] = hi;
    g_xl[idx] = __float2half_rn(v - __half2float(hi));
}

__global__ void prep_misc(const float* __restrict__ bih, const float* __restrict__ bhh) {
    int i = blockIdx.x * blockDim.x + threadIdx.x;
    if (i < BB * HH) {
        g_hh[0][i] = __float2half_rn(0.f);
        g_c[i] = 0.f;
    }
    if (i < GG) g_bs[i] = bih[i] + bhh[i];
    if (i < 8) g_gc[i] = 0u;
}

// ---------------- xg precompute: xg[t] = (xhi+xlo) @ Wih_perm^T -----------------
// Grid (32 nt, 512 t), 512 thr (16 warps = 8m x 2n). CTA tile M=128, N=128, K=256.
__global__ __launch_bounds__(NTHR, 1) void xg_gemm() {
    extern __shared__ __align__(16) char dsm_raw[];
    const uint32_t dbase = (smem_u32(dsm_raw) + 127) & ~127u;

    const int tid = threadIdx.x;
    const int wid = tid >> 5, lid = tid & 31;
    const int wm = wid >> 1, wn = wid & 1;
    const int nt = blockIdx.x;      // 128-col gate tile
    const int t  = blockIdx.y;
    const int mi = lid >> 3, lr = lid & 7;

    const __half* __restrict__ xsh = g_xh + (size_t)t * (BB * II);
    const __half* __restrict__ xsl = g_xl + (size_t)t * (BB * II);

    // load B (W rows nt*128.., k 0..255) and A (x hi/lo), 4096 units each
#pragma unroll
    for (int s = 0; s < 8; s++) {
        int idx = tid + NTHR * s;           // 0..4095
        int row = idx >> 5, seg = idx & 31;
        uint32_t so = (uint32_t)(seg >> 3) * 16384u + (uint32_t)row * 128u
                    + (uint32_t)(((seg & 7) ^ (row & 7)) << 4);
        cp16(dbase + PRE_B + so, g_Wh + (size_t)(nt * 128 + row) * KTOT + seg * 8);
        cp16(dbase + PRE_AH + so, xsh + (size_t)row * II + seg * 8);
        cp16(dbase + PRE_AL + so, xsl + (size_t)row * II + seg * 8);
    }
    asm volatile("cp.async.commit_group;" ::: "memory");
    asm volatile("cp.async.wait_group 0;" ::: "memory");
    __syncthreads();

    float acc[8][4];
#pragma unroll
    for (int j = 0; j < 8; j++)
#pragma unroll
        for (int i = 0; i < 4; i++) acc[j][i] = 0.f;

    const int arow = wm * 16 + ((mi & 1) << 3) + lr;
    const int axor = arow & 7;

#pragma unroll
    for (int ks = 0; ks < 16; ks++) {
        uint32_t ah[4], al[4];
        {
            int ksega = (ks & 3) * 2 + (mi >> 1);
            uint32_t ad = dbase + PRE_AH + (uint32_t)(ks >> 2) * 16384u
                        + (uint32_t)arow * 128u + (uint32_t)((ksega ^ axor) << 4);
            ldsm4(ad, ah[0], ah[1], ah[2], ah[3]);
            ldsm4(ad + (PRE_AL - PRE_AH), al[0], al[1], al[2], al[3]);
        }
#pragma unroll
        for (int g = 0; g < 4; g++) {
            int brow = wn * 64 + g * 16 + ((mi >> 1) << 3) + lr;
            int ksegb = (ks & 3) * 2 + (mi & 1);
            uint32_t bd = dbase + PRE_B + (uint32_t)(ks >> 2) * 16384u
                        + (uint32_t)brow * 128u + (uint32_t)((ksegb ^ (brow & 7)) << 4);
            uint32_t bh[4];
            ldsm4(bd, bh[0], bh[1], bh[2], bh[3]);
            mma16816(acc[g * 2 + 0], ah, bh[0], bh[1]);
            mma16816(acc[g * 2 + 1], ah, bh[2], bh[3]);
            mma16816(acc[g * 2 + 0], al, bh[0], bh[1]);
            mma16816(acc[g * 2 + 1], al, bh[2], bh[3]);
        }
    }

    // write xg in [t][nb][m][32] layout (fragment order preserved)
    const int lq = lid & 3;
#pragma unroll
    for (int j = 0; j < 8; j++) {
        int c = wn * 64 + (j >> 1) * 16 + (j & 1) * 8 + lq * 2;
        int C = nt * 128 + c;
        int nbv = C >> 5, c31 = C & 31;
#pragma unroll
        for (int r = 0; r < 2; r++) {
            int m = wm * 16 + (lid >> 2) + r * 8;
            size_t idx = (((size_t)t * NCTA + nbv) * 128 + m) * 32 + c31;
            float2 v = make_float2(acc[j][r * 2], acc[j][r * 2 + 1]);
            *reinterpret_cast<float2*>(g_xg + idx) = v;
        }
    }
}

// ---------------- persistent LSTM recurrence -----------------------------------
// 128 CTAs x 512 thr (16 warps = 8m x 2n). CTA: M=128, N=32 gate cols = 8 h-cols.
// gates = xg[t] (precomputed) + h_fp16 @ Whh_hi (fp32 accum).
// Chunk j (h cols 128j..) produced by CTA group j = nb>>4; rotated consumption.
__global__ __launch_bounds__(NTHR, 1) void lstm_persist() {
    extern __shared__ __align__(16) char dsm_raw[];
    const uint32_t dbase = (smem_u32(dsm_raw) + 127) & ~127u;

    const int tid = threadIdx.x;
    const int wid = tid >> 5, lid = tid & 31;
    const int wm = wid >> 1, wn = wid & 1;
    const int nb = blockIdx.x;
    const int grp = nb >> 4;                 // producer group 0..7
    const int mi = lid >> 3, lr = lid & 7;

    // ---- load Whh slice (32 rows x k 256..1280) into SMEM once ----
#pragma unroll
    for (int s = 0; s < 8; s++) {
        int idx = tid + NTHR * s;            // 0..4095
        int row = idx >> 7, kseg = idx & 127;
        size_t go = (size_t)(nb * 32 + row) * KTOT + II + kseg * 8;
        uint32_t so = (uint32_t)row * 2048u + (uint32_t)(kseg >> 3) * 128u
                    + (uint32_t)(((kseg & 7) ^ (row & 7)) << 4);
        cp16(dbase + W_HI + so, g_Wh + go);
    }
    asm volatile("cp.async.commit_group;" ::: "memory");

    const int lq = lid & 3;
    const bool hasIF = (lq & 1) == 0;
    const int hcl = lq >> 1;

    const int arow = wm * 16 + ((mi & 1) << 3) + lr;
    const uint32_t aoff = (uint32_t)arow * 128u;
    const int axor = arow & 7;
    const int brow = wn * 16 + ((mi >> 1) << 3) + lr;
    const uint32_t bbase0 = dbase + W_HI + (uint32_t)brow * 2048u;
    const int bxor = brow & 7;

#pragma unroll 1
    for (int t = 0; t < TT; t++) {
        const __half* __restrict__ hsh = g_hh[t & 1];
        const unsigned need = 16u * (unsigned)t;

        // xg accumulator-init loads (independent; issue first, consumed at epilogue)
        float2 xgv[2][2];
        {
            const float* xb = g_xg + (((size_t)t * NCTA + nb) * 128) * 32;
            const int r0 = wm * 16 + (lid >> 2);
            const int c0 = wn * 16 + lq * 2;
#pragma unroll
            for (int nf = 0; nf < 2; nf++)
#pragma unroll
                for (int r = 0; r < 2; r++)
                    xgv[nf][r] = *reinterpret_cast<const float2*>(
                        xb + (size_t)(r0 + r * 8) * 32 + c0 + nf * 8);
        }

        // chunk loader with rotation + readiness poll (all threads poll)
        auto wait_load = [&](int i) {
            const int ck = (grp + i) & 7;
            gwait(ck, need);
            const uint32_t bofs = A_BUF + (uint32_t)(i & 1) * ABUF_STRIDE;
#pragma unroll
            for (int s = 0; s < 4; s++) {
                int idx = tid + NTHR * s;    // 0..2047
                int row = idx >> 4, seg = idx & 15;
                uint32_t sa = dbase + bofs + (uint32_t)(seg >> 3) * 16384u
                            + (uint32_t)row * 128u
                            + (uint32_t)(((seg & 7) ^ (row & 7)) << 4);
                cp16(sa, hsh + (size_t)row * HH + ck * 128 + seg * 8);
            }
            asm volatile("cp.async.commit_group;" ::: "memory");
        };

        float acc[2][4];
#pragma unroll
        for (int a = 0; a < 2; a++)
#pragma unroll
            for (int i = 0; i < 4; i++) acc[a][i] = 0.f;

        wait_load(0);
        wait_load(1);

#pragma unroll 1
        for (int i = 0; i < NCHUNK_H; i++) {
            if (i + 1 < NCHUNK_H) asm volatile("cp.async.wait_group 1;" ::: "memory");
            else                  asm volatile("cp.async.wait_group 0;" ::: "memory");
            __syncthreads();

            const int ck = (grp + i) & 7;
            const uint32_t abase = dbase + A_BUF + (uint32_t)(i & 1) * ABUF_STRIDE;

#pragma unroll
            for (int ks = 0; ks < 8; ks++) {
                uint32_t ah[4];
                {
                    int ksega = (ks & 3) * 2 + (mi >> 1);
                    uint32_t ad = abase + (uint32_t)(ks >> 2) * 16384u + aoff
                                + (uint32_t)((ksega ^ axor) << 4);
                    ldsm4(ad, ah[0], ah[1], ah[2], ah[3]);
                }
                uint32_t bh[4];
                {
                    int kseg = ck * 16 + ks * 2 + (mi & 1);
                    uint32_t bd = bbase0 + (uint32_t)(kseg >> 3) * 128u
                                + (uint32_t)(((kseg & 7) ^ bxor) << 4);
                    ldsm4(bd, bh[0], bh[1], bh[2], bh[3]);
                }
                mma16816(acc[0], ah, bh[0], bh[1]);
                mma16816(acc[1], ah, bh[2], bh[3]);
            }
            __syncthreads();
            if (i + 2 < NCHUNK_H) wait_load(i + 2);
        }

        // ---- epilogue: xg + bias + LSTM update, write h(t+1) ----
        __half* __restrict__ hh_o = g_hh[(t + 1) & 1];
        const int rbase = wm * 16 + (lid >> 2);
#pragma unroll
        for (int nf = 0; nf < 2; nf++) {
            const int nglob = nb * 8 + wn * 4 + nf * 2 + hcl;
            const float bias0 = g_bs[(hasIF ? 0 : 2) * HH + nglob];
            const float bias1 = g_bs[(hasIF ? 1 : 3) * HH + nglob];
            float d0 = acc[nf][0] + xgv[nf][0].x + bias0;
            float d1 = acc[nf][1] + xgv[nf][0].y + bias1;
            float d2 = acc[nf][2] + xgv[nf][1].x + bias0;
            float d3 = acc[nf][3] + xgv[nf][1].y + bias1;
            float e0 = __shfl_xor_sync(0xFFFFFFFFu, d0, 1);
            float e1 = __shfl_xor_sync(0xFFFFFFFFu, d1, 1);
            float e2 = __shfl_xor_sync(0xFFFFFFFFu, d2, 1);
            float e3 = __shfl_xor_sync(0xFFFFFFFFu, d3, 1);
            if (hasIF) {
#pragma unroll
                for (int r = 0; r < 2; r++) {
                    float gi = r ? d2 : d0, gf = r ? d3 : d1;
                    float gg = r ? e2 : e0, go = r ? e3 : e1;
                    float iv = 1.f / (1.f + expf(-gi));
                    float fv = 1.f / (1.f + expf(-gf));
                    float gv = tanhf(gg);
                    float ov = 1.f / (1.f + expf(-go));
                    size_t idx = (size_t)(rbase + r * 8) * HH + nglob;
                    float cn = fv * g_c[idx] + iv * gv;
                    g_c[idx] = cn;
                    float hv = ov * tanhf(cn);
                    hh_o[idx] = __float2half_rn(hv);
                }
            }
        }
        __threadfence();
        __syncthreads();
        if (tid == 0) {
            unsigned dummy;
            asm volatile("atom.release.gpu.global.add.u32 %0, [%1], 1;"
                         : "=r"(dummy) : "l"(&g_gc[grp]) : "memory");
        }
    }
}

// ---------------- final FC ------------------------------------------------------
__global__ __launch_bounds__(256) void fc_kernel(
    const float* __restrict__ fcW, const float* __restrict__ fcb, float* __restrict__ out) {
    int w = blockIdx.x * 8 + (threadIdx.x >> 5);
    int lane = threadIdx.x & 31;
    if (w >= BB * CC) return;
    int b = w / CC, c = w - b * CC;
    const __half* __restrict__ hh = g_hh[0] + (size_t)b * HH;   // TT even
    const float* __restrict__ wr = fcW + (size_t)c * HH;
    float s = 0.f;
#pragma unroll 4
    for (int k = lane; k < HH; k += 32)
        s += __half2float(hh[k]) * wr[k];
#pragma unroll
    for (int o = 16; o; o >>= 1) s += __shfl_down_sync(0xFFFFFFFFu, s, o);
    if (lane == 0) out[b * CC + c] = s + fcb[c];
}

extern "C" void kernel_launch(void* const* d_in, const int* in_sizes, int n_in,
                              void* d_out, int out_size) {
    const float* x   = (const float*)d_in[0];
    const float* Wih = (const float*)d_in[1];
    const float* Whh = (const float*)d_in[2];
    const float* bih = (const float*)d_in[3];
    const float* bhh = (const float*)d_in[4];
    const float* fcW = (const float*)d_in[5];
    const float* fcb = (const float*)d_in[6];
    float* out = (float*)d_out;

    cudaFuncSetAttribute(xg_gemm, cudaFuncAttributeMaxDynamicSharedMemorySize, SMEM_PRE);
    cudaFuncSetAttribute(lstm_persist, cudaFuncAttributeMaxDynamicSharedMemorySize, SMEM_DYN);

    prep_w<<<(GG * KTOT + 255) / 256, 256>>>(Wih, Whh);
    prep_x<<<(TT * BB * II + 255) / 256, 256>>>(x);
    prep_misc<<<(BB * HH + 255) / 256, 256>>>(bih, bhh);
    xg_gemm<<<dim3(32, TT, 1), NTHR, SMEM_PRE>>>();
    lstm_persist<<<NCTA, NTHR, SMEM_DYN>>>();
    fc_kernel<<<(BB * CC + 7) / 8, 256>>>(fcW, fcb, out);
}

// round 10
// speedup vs baseline: 1.0244x; 1.0244x over previous
#include <cuda_runtime.h>
#include <cuda_fp16.h>
#include <cstdint>
#include <math.h>

#define BB 128
#define TT 512
#define II 256
#define HH 1024
#define GG 4096
#define CC 1000
#define KTOT 1280
#define NCTA 128
#define NTHR 512
#define NCHUNK_H 8         // h-part K=1024 in 8 chunks of 128

// Persistent kernel SMEM: Whh slice 32x1024 fp16 (2048B rows) + A triple buf
#define W_HI 0u
#define A_BUF 65536u
#define ABUF_STRIDE 32768u
#define SMEM_DYN (65536 + 3 * 32768 + 256)

// Precompute kernel SMEM: B 64K | A_hi 64K | A_lo 64K
#define PRE_B  0u
#define PRE_AH 65536u
#define PRE_AL 131072u
#define SMEM_PRE (196608 + 256)

// ---------------- device globals (no dynamic alloc) ---------------------------
__device__ __align__(16) __half g_Wh[GG * KTOT];            // weights fp16, permuted
__device__ __align__(16) __half g_xh[TT * BB * II];         // x hi, [t][m][k]
__device__ __align__(16) __half g_xl[TT * BB * II];         // x lo
__device__ __align__(16) __half g_hh[2][BB * HH];           // h fp16 ping-pong
__device__ float g_c[BB * HH];
__device__ float g_bs[GG];
__device__ float g_xg[268435456];                           // [t][nb][m][32] = 1 GB
__device__ unsigned g_gc[8 * 32];                           // counters, 128B apart

// ---------------- helpers ------------------------------------------------------
__device__ __forceinline__ uint32_t smem_u32(const void* p) {
    uint32_t a;
    asm("{ .reg .u64 t; cvta.to.shared.u64 t, %1; cvt.u32.u64 %0, t; }" : "=r"(a) : "l"(p));
    return a;
}
__device__ __forceinline__ void cp16(uint32_t saddr, const void* gaddr) {
    asm volatile("cp.async.cg.shared.global [%0], [%1], 16;" :: "r"(saddr), "l"(gaddr) : "memory");
}
__device__ __forceinline__ void ldsm4(uint32_t addr, uint32_t& r0, uint32_t& r1,
                                      uint32_t& r2, uint32_t& r3) {
    asm volatile("ldmatrix.sync.aligned.m8n8.x4.shared.b16 {%0,%1,%2,%3}, [%4];"
                 : "=r"(r0), "=r"(r1), "=r"(r2), "=r"(r3) : "r"(addr));
}
__device__ __forceinline__ void mma16816(float* c, const uint32_t* a, uint32_t b0, uint32_t b1) {
    asm volatile(
        "mma.sync.aligned.m16n8k16.row.col.f32.f16.f16.f32 "
        "{%0,%1,%2,%3}, {%4,%5,%6,%7}, {%8,%9}, {%0,%1,%2,%3};"
        : "+f"(c[0]), "+f"(c[1]), "+f"(c[2]), "+f"(c[3])
        : "r"(a[0]), "r"(a[1]), "r"(a[2]), "r"(a[3]), "r"(b0), "r"(b1));
}

// ---------------- prep kernels -------------------------------------------------
// Stored row r = nb*32 + hc*4 + q  <->  original row q*H + nb*8 + hc.
__global__ void prep_w(const float* __restrict__ Wih, const float* __restrict__ Whh) {
    int idx = blockIdx.x * blockDim.x + threadIdx.x;
    if (idx >= GG * KTOT) return;
    int r = idx / KTOT, k = idx - r * KTOT;
    int nb = r >> 5, j = r & 31, hc = j >> 2, q = j & 3;
    int orig = q * HH + nb * 8 + hc;
    float v = (k < II) ? Wih[(size_t)orig * II + k] : Whh[(size_t)orig * HH + (k - II)];
    g_Wh[idx] = __float2half_rn(v);
}

__global__ void prep_x(const float* __restrict__ x) {
    int idx = blockIdx.x * blockDim.x + threadIdx.x;
    if (idx >= TT * BB * II) return;
    int t = idx / (BB * II);
    int rem = idx - t * (BB * II);
    int m = rem / II, k = rem - m * II;
    float v = x[((size_t)m * TT + t) * II + k];
    __half hi = __float2half_rn(v);
    g_xh[idx] = hi;
    g_xl[idx] = __float2half_rn(v - __half2float(hi));
}

__global__ void prep_misc(const float* __restrict__ bih, const float* __restrict__ bhh) {
    int i = blockIdx.x * blockDim.x + threadIdx.x;
    if (i < BB * HH) {
        g_hh[0][i] = __float2half_rn(0.f);
        g_c[i] = 0.f;
    }
    if (i < GG) g_bs[i] = bih[i] + bhh[i];
    if (i < 8 * 32) g_gc[i] = 0u;
}

// ---------------- xg precompute: xg[t] = (xhi+xlo) @ Wih_perm^T -----------------
__global__ __launch_bounds__(NTHR, 1) void xg_gemm() {
    extern __shared__ __align__(16) char dsm_raw[];
    const uint32_t dbase = (smem_u32(dsm_raw) + 127) & ~127u;

    const int tid = threadIdx.x;
    const int wid = tid >> 5, lid = tid & 31;
    const int wm = wid >> 1, wn = wid & 1;
    const int nt = blockIdx.x;      // 128-col gate tile
    const int t  = blockIdx.y;
    const int mi = lid >> 3, lr = lid & 7;

    const __half* __restrict__ xsh = g_xh + (size_t)t * (BB * II);
    const __half* __restrict__ xsl = g_xl + (size_t)t * (BB * II);

#pragma unroll
    for (int s = 0; s < 8; s++) {
        int idx = tid + NTHR * s;           // 0..4095
        int row = idx >> 5, seg = idx & 31;
        uint32_t so = (uint32_t)(seg >> 3) * 16384u + (uint32_t)row * 128u
                    + (uint32_t)(((seg & 7) ^ (row & 7)) << 4);
        cp16(dbase + PRE_B + so, g_Wh + (size_t)(nt * 128 + row) * KTOT + seg * 8);
        cp16(dbase + PRE_AH + so, xsh + (size_t)row * II + seg * 8);
        cp16(dbase + PRE_AL + so, xsl + (size_t)row * II + seg * 8);
    }
    asm volatile("cp.async.commit_group;" ::: "memory");
    asm volatile("cp.async.wait_group 0;" ::: "memory");
    __syncthreads();

    float acc[8][4];
#pragma unroll
    for (int j = 0; j < 8; j++)
#pragma unroll
        for (int i = 0; i < 4; i++) acc[j][i] = 0.f;

    const int arow = wm * 16 + ((mi & 1) << 3) + lr;
    const int axor = arow & 7;

#pragma unroll
    for (int ks = 0; ks < 16; ks++) {
        uint32_t ah[4], al[4];
        {
            int ksega = (ks & 3) * 2 + (mi >> 1);
            uint32_t ad = dbase + PRE_AH + (uint32_t)(ks >> 2) * 16384u
                        + (uint32_t)arow * 128u + (uint32_t)((ksega ^ axor) << 4);
            ldsm4(ad, ah[0], ah[1], ah[2], ah[3]);
            ldsm4(ad + (PRE_AL - PRE_AH), al[0], al[1], al[2], al[3]);
        }
#pragma unroll
        for (int g = 0; g < 4; g++) {
            int brow = wn * 64 + g * 16 + ((mi >> 1) << 3) + lr;
            int ksegb = (ks & 3) * 2 + (mi & 1);
            uint32_t bd = dbase + PRE_B + (uint32_t)(ks >> 2) * 16384u
                        + (uint32_t)brow * 128u + (uint32_t)((ksegb ^ (brow & 7)) << 4);
            uint32_t bh[4];
            ldsm4(bd, bh[0], bh[1], bh[2], bh[3]);
            mma16816(acc[g * 2 + 0], ah, bh[0], bh[1]);
            mma16816(acc[g * 2 + 1], ah, bh[2], bh[3]);
            mma16816(acc[g * 2 + 0], al, bh[0], bh[1]);
            mma16816(acc[g * 2 + 1], al, bh[2], bh[3]);
        }
    }

    const int lq = lid & 3;
#pragma unroll
    for (int j = 0; j < 8; j++) {
        int c = wn * 64 + (j >> 1) * 16 + (j & 1) * 8 + lq * 2;
        int C = nt * 128 + c;
        int nbv = C >> 5, c31 = C & 31;
#pragma unroll
        for (int r = 0; r < 2; r++) {
            int m = wm * 16 + (lid >> 2) + r * 8;
            size_t idx = (((size_t)t * NCTA + nbv) * 128 + m) * 32 + c31;
            *reinterpret_cast<float2*>(g_xg + idx) =
                make_float2(acc[j][r * 2], acc[j][r * 2 + 1]);
        }
    }
}

// ---------------- persistent LSTM recurrence -----------------------------------
// 128 CTAs x 512 thr (16 warps = 8m x 2n). CTA: M=128, N=32 gate cols = 8 h-cols.
// gates = xg[t] + h_fp16 @ Whh_hi (fp32 accum). Chunk j produced by group j=nb>>4;
// rotated consumption; tid0-only counter polling; triple-buffered A.
__global__ __launch_bounds__(NTHR, 1) void lstm_persist() {
    extern __shared__ __align__(16) char dsm_raw[];
    const uint32_t dbase = (smem_u32(dsm_raw) + 127) & ~127u;

    const int tid = threadIdx.x;
    const int wid = tid >> 5, lid = tid & 31;
    const int wm = wid >> 1, wn = wid & 1;
    const int nb = blockIdx.x;
    const int grp = nb >> 4;                 // producer group 0..7
    const int mi = lid >> 3, lr = lid & 7;

    // ---- load Whh slice (32 rows x k 256..1280) into SMEM once ----
#pragma unroll
    for (int s = 0; s < 8; s++) {
        int idx = tid + NTHR * s;            // 0..4095
        int row = idx >> 7, kseg = idx & 127;
        size_t go = (size_t)(nb * 32 + row) * KTOT + II + kseg * 8;
        uint32_t so = (uint32_t)row * 2048u + (uint32_t)(kseg >> 3) * 128u
                    + (uint32_t)(((kseg & 7) ^ (row & 7)) << 4);
        cp16(dbase + W_HI + so, g_Wh + go);
    }
    asm volatile("cp.async.commit_group;" ::: "memory");

    const int lq = lid & 3;
    const bool hasIF = (lq & 1) == 0;
    const int hcl = lq >> 1;

    const int arow = wm * 16 + ((mi & 1) << 3) + lr;
    const uint32_t aoff = (uint32_t)arow * 128u;
    const int axor = arow & 7;
    const int brow = wn * 16 + ((mi >> 1) << 3) + lr;
    const uint32_t bbase0 = dbase + W_HI + (uint32_t)brow * 2048u;
    const int bxor = brow & 7;

#pragma unroll 1
    for (int t = 0; t < TT; t++) {
        const __half* __restrict__ hsh = g_hh[t & 1];
        const unsigned need = 16u * (unsigned)t;

        // xg accumulator-init loads (independent; consumed at epilogue)
        float2 xgv[2][2];
        {
            const float* xb = g_xg + (((size_t)t * NCTA + nb) * 128) * 32;
            const int r0 = wm * 16 + (lid >> 2);
            const int c0 = wn * 16 + lq * 2;
#pragma unroll
            for (int nf = 0; nf < 2; nf++)
#pragma unroll
                for (int r = 0; r < 2; r++)
                    xgv[nf][r] = *reinterpret_cast<const float2*>(
                        xb + (size_t)(r0 + r * 8) * 32 + c0 + nf * 8);
        }

        // tid0-only readiness poll, then whole-CTA load into buffer i%3
        auto wait_load = [&](int i) {
            const int ck = (grp + i) & 7;
            if (tid == 0) {
                unsigned v;
                do {
                    asm volatile("ld.acquire.gpu.global.u32 %0, [%1];"
                                 : "=r"(v) : "l"(&g_gc[ck << 5]) : "memory");
                } while (v < need);
            }
            __syncthreads();
            const uint32_t bofs = A_BUF + (uint32_t)(i % 3) * ABUF_STRIDE;
#pragma unroll
            for (int s = 0; s < 4; s++) {
                int idx = tid + NTHR * s;    // 0..2047
                int row = idx >> 4, seg = idx & 15;
                uint32_t sa = dbase + bofs + (uint32_t)(seg >> 3) * 16384u
                            + (uint32_t)row * 128u
                            + (uint32_t)(((seg & 7) ^ (row & 7)) << 4);
                cp16(sa, hsh + (size_t)row * HH + ck * 128 + seg * 8);
            }
            asm volatile("cp.async.commit_group;" ::: "memory");
        };

        float acc[2][4];
#pragma unroll
        for (int a = 0; a < 2; a++)
#pragma unroll
            for (int i = 0; i < 4; i++) acc[a][i] = 0.f;

        wait_load(0);
        wait_load(1);
        wait_load(2);

#pragma unroll 1
        for (int i = 0; i < NCHUNK_H; i++) {
            if (i + 2 < NCHUNK_H)      asm volatile("cp.async.wait_group 2;" ::: "memory");
            else if (i + 1 < NCHUNK_H) asm volatile("cp.async.wait_group 1;" ::: "memory");
            else                       asm volatile("cp.async.wait_group 0;" ::: "memory");
            __syncthreads();

            const int ck = (grp + i) & 7;
            const uint32_t abase = dbase + A_BUF + (uint32_t)(i % 3) * ABUF_STRIDE;

#pragma unroll
            for (int ks = 0; ks < 8; ks++) {
                uint32_t ah[4];
                {
                    int ksega = (ks & 3) * 2 + (mi >> 1);
                    uint32_t ad = abase + (uint32_t)(ks >> 2) * 16384u + aoff
                                + (uint32_t)((ksega ^ axor) << 4);
                    ldsm4(ad, ah[0], ah[1], ah[2], ah[3]);
                }
                uint32_t bh[4];
                {
                    int kseg = ck * 16 + ks * 2 + (mi & 1);
                    uint32_t bd = bbase0 + (uint32_t)(kseg >> 3) * 128u
                                + (uint32_t)(((kseg & 7) ^ bxor) << 4);
                    ldsm4(bd, bh[0], bh[1], bh[2], bh[3]);
                }
                mma16816(acc[0], ah, bh[0], bh[1]);
                mma16816(acc[1], ah, bh[2], bh[3]);
            }
            __syncthreads();
            if (i + 3 < NCHUNK_H) wait_load(i + 3);
        }

        // ---- epilogue: xg + bias + LSTM update, write h(t+1) ----
        __half* __restrict__ hh_o = g_hh[(t + 1) & 1];
        const int rbase = wm * 16 + (lid >> 2);
#pragma unroll
        for (int nf = 0; nf < 2; nf++) {
            const int nglob = nb * 8 + wn * 4 + nf * 2 + hcl;
            const float bias0 = g_bs[(hasIF ? 0 : 2) * HH + nglob];
            const float bias1 = g_bs[(hasIF ? 1 : 3) * HH + nglob];
            float d0 = acc[nf][0] + xgv[nf][0].x + bias0;
            float d1 = acc[nf][1] + xgv[nf][0].y + bias1;
            float d2 = acc[nf][2] + xgv[nf][1].x + bias0;
            float d3 = acc[nf][3] + xgv[nf][1].y + bias1;
            float e0 = __shfl_xor_sync(0xFFFFFFFFu, d0, 1);
            float e1 = __shfl_xor_sync(0xFFFFFFFFu, d1, 1);
            float e2 = __shfl_xor_sync(0xFFFFFFFFu, d2, 1);
            float e3 = __shfl_xor_sync(0xFFFFFFFFu, d3, 1);
            if (hasIF) {
#pragma unroll
                for (int r = 0; r < 2; r++) {
                    float gi = r ? d2 : d0, gf = r ? d3 : d1;
                    float gg = r ? e2 : e0, go = r ? e3 : e1;
                    float iv = 1.f / (1.f + expf(-gi));
                    float fv = 1.f / (1.f + expf(-gf));
                    float gv = tanhf(gg);
                    float ov = 1.f / (1.f + expf(-go));
                    size_t idx = (size_t)(rbase + r * 8) * HH + nglob;
                    float cn = fv * g_c[idx] + iv * gv;
                    g_c[idx] = cn;
                    float hv = ov * tanhf(cn);
                    hh_o[idx] = __float2half_rn(hv);
                }
            }
        }
        __threadfence();
        __syncthreads();
        if (tid == 0) {
            unsigned dummy;
            asm volatile("atom.release.gpu.global.add.u32 %0, [%1], 1;"
                         : "=r"(dummy) : "l"(&g_gc[grp << 5]) : "memory");
        }
    }
}

// ---------------- final FC ------------------------------------------------------
__global__ __launch_bounds__(256) void fc_kernel(
    const float* __restrict__ fcW, const float* __restrict__ fcb, float* __restrict__ out) {
    int w = blockIdx.x * 8 + (threadIdx.x >> 5);
    int lane = threadIdx.x & 31;
    if (w >= BB * CC) return;
    int b = w / CC, c = w - b * CC;
    const __half* __restrict__ hh = g_hh[0] + (size_t)b * HH;   // TT even
    const float* __restrict__ wr = fcW + (size_t)c * HH;
    float s = 0.f;
#pragma unroll 4
    for (int k = lane; k < HH; k += 32)
        s += __half2float(hh[k]) * wr[k];
#pragma unroll
    for (int o = 16; o; o >>= 1) s += __shfl_down_sync(0xFFFFFFFFu, s, o);
    if (lane == 0) out[b * CC + c] = s + fcb[c];
}

extern "C" void kernel_launch(void* const* d_in, const int* in_sizes, int n_in,
                              void* d_out, int out_size) {
    const float* x   = (const float*)d_in[0];
    const float* Wih = (const float*)d_in[1];
    const float* Whh = (const float*)d_in[2];
    const float* bih = (const float*)d_in[3];
    const float* bhh = (const float*)d_in[4];
    const float* fcW = (const float*)d_in[5];
    const float* fcb = (const float*)d_in[6];
    float* out = (float*)d_out;

    cudaFuncSetAttribute(xg_gemm, cudaFuncAttributeMaxDynamicSharedMemorySize, SMEM_PRE);
    cudaFuncSetAttribute(lstm_persist, cudaFuncAttributeMaxDynamicSharedMemorySize, SMEM_DYN);

    prep_w<<<(GG * KTOT + 255) / 256, 256>>>(Wih, Whh);
    prep_x<<<(TT * BB * II + 255) / 256, 256>>>(x);
    prep_misc<<<(BB * HH + 255) / 256, 256>>>(bih, bhh);
    xg_gemm<<<dim3(32, TT, 1), NTHR, SMEM_PRE>>>();
    lstm_persist<<<NCTA, NTHR, SMEM_DYN>>>();
    fc_kernel<<<(BB * CC + 7) / 8, 256>>>(fcW, fcb, out);
}

// round 11
// speedup vs baseline: 1.2048x; 1.1761x over previous
#include <cuda_runtime.h>
#include <cuda_fp16.h>
#include <cstdint>
#include <math.h>

#define BB 128
#define TT 512
#define II 256
#define HH 1024
#define GG 4096
#define CC 1000
#define KTOT 1280
#define NCTA 128
#define NTHR 512           // xg_gemm
#define NTHR_P 256         // persistent recurrence
#define NCHUNK_H 8         // h-part K=1024 in 8 chunks of 128

// Persistent kernel SMEM: Whh slice 32x1024 fp16 (2048B rows) + A quad buffer
#define W_HI 0u
#define A_BUF 65536u
#define ABUF_STRIDE 32768u
#define SMEM_DYN (65536 + 4 * 32768 + 256)

// Precompute kernel SMEM: B 64K | A_hi 64K | A_lo 64K
#define PRE_B  0u
#define PRE_AH 65536u
#define PRE_AL 131072u
#define SMEM_PRE (196608 + 256)

// ---------------- device globals (no dynamic alloc) ---------------------------
__device__ __align__(16) __half g_Wh[GG * KTOT];            // weights fp16, permuted
__device__ __align__(16) __half g_xh[TT * BB * II];         // x hi, [t][m][k]
__device__ __align__(16) __half g_xl[TT * BB * II];         // x lo
__device__ __align__(16) __half g_hh[2][BB * HH];           // h fp16 ping-pong
__device__ float g_bs[GG];
__device__ float g_xg[268435456];                           // [t][nb][m][32] = 1 GB
__device__ unsigned g_gc[8 * 32];                           // counters, 128B apart

// ---------------- helpers ------------------------------------------------------
__device__ __forceinline__ uint32_t smem_u32(const void* p) {
    uint32_t a;
    asm("{ .reg .u64 t; cvta.to.shared.u64 t, %1; cvt.u32.u64 %0, t; }" : "=r"(a) : "l"(p));
    return a;
}
__device__ __forceinline__ void cp16(uint32_t saddr, const void* gaddr) {
    asm volatile("cp.async.cg.shared.global [%0], [%1], 16;" :: "r"(saddr), "l"(gaddr) : "memory");
}
__device__ __forceinline__ void ldsm4(uint32_t addr, uint32_t& r0, uint32_t& r1,
                                      uint32_t& r2, uint32_t& r3) {
    asm volatile("ldmatrix.sync.aligned.m8n8.x4.shared.b16 {%0,%1,%2,%3}, [%4];"
                 : "=r"(r0), "=r"(r1), "=r"(r2), "=r"(r3) : "r"(addr));
}
__device__ __forceinline__ void mma16816(float* c, const uint32_t* a, uint32_t b0, uint32_t b1) {
    asm volatile(
        "mma.sync.aligned.m16n8k16.row.col.f32.f16.f16.f32 "
        "{%0,%1,%2,%3}, {%4,%5,%6,%7}, {%8,%9}, {%0,%1,%2,%3};"
        : "+f"(c[0]), "+f"(c[1]), "+f"(c[2]), "+f"(c[3])
        : "r"(a[0]), "r"(a[1]), "r"(a[2]), "r"(a[3]), "r"(b0), "r"(b1));
}

// ---------------- prep kernels -------------------------------------------------
// Stored row r = nb*32 + hc*4 + q  <->  original row q*H + nb*8 + hc.
__global__ void prep_w(const float* __restrict__ Wih, const float* __restrict__ Whh) {
    int idx = blockIdx.x * blockDim.x + threadIdx.x;
    if (idx >= GG * KTOT) return;
    int r = idx / KTOT, k = idx - r * KTOT;
    int nb = r >> 5, j = r & 31, hc = j >> 2, q = j & 3;
    int orig = q * HH + nb * 8 + hc;
    float v = (k < II) ? Wih[(size_t)orig * II + k] : Whh[(size_t)orig * HH + (k - II)];
    g_Wh[idx] = __float2half_rn(v);
}

__global__ void prep_x(const float* __restrict__ x) {
    int idx = blockIdx.x * blockDim.x + threadIdx.x;
    if (idx >= TT * BB * II) return;
    int t = idx / (BB * II);
    int rem = idx - t * (BB * II);
    int m = rem / II, k = rem - m * II;
    float v = x[((size_t)m * TT + t) * II + k];
    __half hi = __float2half_rn(v);
    g_xh[idx] = hi;
    g_xl[idx] = __float2half_rn(v - __half2float(hi));
}

__global__ void prep_misc(const float* __restrict__ bih, const float* __restrict__ bhh) {
    int i = blockIdx.x * blockDim.x + threadIdx.x;
    if (i < BB * HH) g_hh[0][i] = __float2half_rn(0.f);
    if (i < GG) g_bs[i] = bih[i] + bhh[i];
    if (i < 8 * 32) g_gc[i] = 0u;
}

// ---------------- xg precompute: xg[t] = (xhi+xlo) @ Wih_perm^T -----------------
__global__ __launch_bounds__(NTHR, 1) void xg_gemm() {
    extern __shared__ __align__(16) char dsm_raw[];
    const uint32_t dbase = (smem_u32(dsm_raw) + 127) & ~127u;

    const int tid = threadIdx.x;
    const int wid = tid >> 5, lid = tid & 31;
    const int wm = wid >> 1, wn = wid & 1;
    const int nt = blockIdx.x;      // 128-col gate tile
    const int t  = blockIdx.y;
    const int mi = lid >> 3, lr = lid & 7;

    const __half* __restrict__ xsh = g_xh + (size_t)t * (BB * II);
    const __half* __restrict__ xsl = g_xl + (size_t)t * (BB * II);

#pragma unroll
    for (int s = 0; s < 8; s++) {
        int idx = tid + NTHR * s;           // 0..4095
        int row = idx >> 5, seg = idx & 31;
        uint32_t so = (uint32_t)(seg >> 3) * 16384u + (uint32_t)row * 128u
                    + (uint32_t)(((seg & 7) ^ (row & 7)) << 4);
        cp16(dbase + PRE_B + so, g_Wh + (size_t)(nt * 128 + row) * KTOT + seg * 8);
        cp16(dbase + PRE_AH + so, xsh + (size_t)row * II + seg * 8);
        cp16(dbase + PRE_AL + so, xsl + (size_t)row * II + seg * 8);
    }
    asm volatile("cp.async.commit_group;" ::: "memory");
    asm volatile("cp.async.wait_group 0;" ::: "memory");
    __syncthreads();

    float acc[8][4];
#pragma unroll
    for (int j = 0; j < 8; j++)
#pragma unroll
        for (int i = 0; i < 4; i++) acc[j][i] = 0.f;

    const int arow = wm * 16 + ((mi & 1) << 3) + lr;
    const int axor = arow & 7;

#pragma unroll
    for (int ks = 0; ks < 16; ks++) {
        uint32_t ah[4], al[4];
        {
            int ksega = (ks & 3) * 2 + (mi >> 1);
            uint32_t ad = dbase + PRE_AH + (uint32_t)(ks >> 2) * 16384u
                        + (uint32_t)arow * 128u + (uint32_t)((ksega ^ axor) << 4);
            ldsm4(ad, ah[0], ah[1], ah[2], ah[3]);
            ldsm4(ad + (PRE_AL - PRE_AH), al[0], al[1], al[2], al[3]);
        }
#pragma unroll
        for (int g = 0; g < 4; g++) {
            int brow = wn * 64 + g * 16 + ((mi >> 1) << 3) + lr;
            int ksegb = (ks & 3) * 2 + (mi & 1);
            uint32_t bd = dbase + PRE_B + (uint32_t)(ks >> 2) * 16384u
                        + (uint32_t)brow * 128u + (uint32_t)((ksegb ^ (brow & 7)) << 4);
            uint32_t bh[4];
            ldsm4(bd, bh[0], bh[1], bh[2], bh[3]);
            mma16816(acc[g * 2 + 0], ah, bh[0], bh[1]);
            mma16816(acc[g * 2 + 1], ah, bh[2], bh[3]);
            mma16816(acc[g * 2 + 0], al, bh[0], bh[1]);
            mma16816(acc[g * 2 + 1], al, bh[2], bh[3]);
        }
    }

    const int lq = lid & 3;
#pragma unroll
    for (int j = 0; j < 8; j++) {
        int c = wn * 64 + (j >> 1) * 16 + (j & 1) * 8 + lq * 2;
        int C = nt * 128 + c;
        int nbv = C >> 5, c31 = C & 31;
#pragma unroll
        for (int r = 0; r < 2; r++) {
            int m = wm * 16 + (lid >> 2) + r * 8;
            size_t idx = (((size_t)t * NCTA + nbv) * 128 + m) * 32 + c31;
            *reinterpret_cast<float2*>(g_xg + idx) =
                make_float2(acc[j][r * 2], acc[j][r * 2 + 1]);
        }
    }
}

// ---------------- persistent LSTM recurrence -----------------------------------
// 128 CTAs x 256 thr (8 warps = 4m x 2n, warp tile 32x16). CTA: M=128, N=32 gate
// cols = 8 h-cols. gates = xg[t] + h_fp16 @ Whh_hi. c-state lives in registers.
__global__ __launch_bounds__(NTHR_P, 1) void lstm_persist() {
    extern __shared__ __align__(16) char dsm_raw[];
    const uint32_t dbase = (smem_u32(dsm_raw) + 127) & ~127u;

    const int tid = threadIdx.x;
    const int wid = tid >> 5, lid = tid & 31;
    const int wm = wid >> 1, wn = wid & 1;   // 4 m-groups x 2 n-groups
    const int nb = blockIdx.x;
    const int grp = nb >> 4;                 // producer group 0..7
    const int mi = lid >> 3, lr = lid & 7;

    // ---- load Whh slice (32 rows x k 256..1280) into SMEM once ----
#pragma unroll
    for (int s = 0; s < 16; s++) {
        int idx = tid + NTHR_P * s;          // 0..4095
        int row = idx >> 7, kseg = idx & 127;
        size_t go = (size_t)(nb * 32 + row) * KTOT + II + kseg * 8;
        uint32_t so = (uint32_t)row * 2048u + (uint32_t)(kseg >> 3) * 128u
                    + (uint32_t)(((kseg & 7) ^ (row & 7)) << 4);
        cp16(dbase + W_HI + so, g_Wh + go);
    }
    asm volatile("cp.async.commit_group;" ::: "memory");

    const int lq = lid & 3;
    const bool hasIF = (lq & 1) == 0;
    const int hcl = lq >> 1;

    // lane-fixed addressing
    const uint32_t aoff0 = (uint32_t)(wm * 32 + ((mi & 1) << 3) + lr) * 128u;
    const int axor = (wm * 32 + ((mi & 1) << 3) + lr) & 7;
    const int brow = wn * 16 + ((mi >> 1) << 3) + lr;
    const uint32_t bbase0 = dbase + W_HI + (uint32_t)brow * 2048u;
    const int bxor = brow & 7;

    float creg[2][2][2];                     // c-state: thread-local forever
#pragma unroll
    for (int a = 0; a < 2; a++)
#pragma unroll
        for (int b = 0; b < 2; b++) { creg[a][b][0] = 0.f; creg[a][b][1] = 0.f; }

#pragma unroll 1
    for (int t = 0; t < TT; t++) {
        const __half* __restrict__ hsh = g_hh[t & 1];
        const unsigned need = 16u * (unsigned)t;

        // xg prefetch (independent; consumed at epilogue)
        float2 xgv[2][2][2];
        {
            const float* xb = g_xg + (((size_t)t * NCTA + nb) * 128) * 32;
            const int c0 = wn * 16 + lq * 2;
#pragma unroll
            for (int mf = 0; mf < 2; mf++) {
                const int r0 = wm * 32 + mf * 16 + (lid >> 2);
#pragma unroll
                for (int nf = 0; nf < 2; nf++)
#pragma unroll
                    for (int r = 0; r < 2; r++)
                        xgv[mf][nf][r] = *reinterpret_cast<const float2*>(
                            xb + (size_t)(r0 + r * 8) * 32 + c0 + nf * 8);
            }
        }

        // issue cp.async for one chunk into buffer i&3 (no barrier inside)
        auto issue_chunk = [&](int i) {
            const int ck = (grp + i) & 7;
            const uint32_t bofs = A_BUF + (uint32_t)(i & 3) * ABUF_STRIDE;
#pragma unroll
            for (int s = 0; s < 8; s++) {
                int idx = tid + NTHR_P * s;  // 0..2047
                int row = idx >> 4, seg = idx & 15;
                uint32_t sa = dbase + bofs + (uint32_t)(seg >> 3) * 16384u
                            + (uint32_t)row * 128u
                            + (uint32_t)(((seg & 7) ^ (row & 7)) << 4);
                cp16(sa, hsh + (size_t)row * HH + ck * 128 + seg * 8);
            }
            asm volatile("cp.async.commit_group;" ::: "memory");
        };
        auto poll_grp = [&](int i) {         // tid0 only
            const int ck = (grp + i) & 7;
            unsigned v;
            do {
                asm volatile("ld.acquire.gpu.global.u32 %0, [%1];"
                             : "=r"(v) : "l"(&g_gc[ck << 5]) : "memory");
            } while (v < need);
        };

        float acc[2][2][4];
#pragma unroll
        for (int a = 0; a < 2; a++)
#pragma unroll
            for (int b = 0; b < 2; b++)
#pragma unroll
                for (int i = 0; i < 4; i++) acc[a][b][i] = 0.f;

        // prologue: poll first 4 groups, one barrier, issue 4 chunks
        if (tid == 0) { poll_grp(0); poll_grp(1); poll_grp(2); poll_grp(3); }
        __syncthreads();
        issue_chunk(0); issue_chunk(1); issue_chunk(2); issue_chunk(3);

#pragma unroll 1
        for (int i = 0; i < NCHUNK_H; i++) {
            {
                int pend = NCHUNK_H - 1 - i; if (pend > 3) pend = 3;
                if (pend == 3)      asm volatile("cp.async.wait_group 3;" ::: "memory");
                else if (pend == 2) asm volatile("cp.async.wait_group 2;" ::: "memory");
                else if (pend == 1) asm volatile("cp.async.wait_group 1;" ::: "memory");
                else                asm volatile("cp.async.wait_group 0;" ::: "memory");
            }
            __syncthreads();

            const int ck = (grp + i) & 7;
            const uint32_t abase = dbase + A_BUF + (uint32_t)(i & 3) * ABUF_STRIDE;

#pragma unroll
            for (int ks = 0; ks < 8; ks++) {
                uint32_t ah[2][4];
                {
                    int ksega = (ks & 3) * 2 + (mi >> 1);
                    uint32_t sw = (uint32_t)((ksega ^ axor) << 4);
                    uint32_t ad = abase + (uint32_t)(ks >> 2) * 16384u + aoff0 + sw;
                    ldsm4(ad, ah[0][0], ah[0][1], ah[0][2], ah[0][3]);
                    ldsm4(ad + 16 * 128u, ah[1][0], ah[1][1], ah[1][2], ah[1][3]);
                }
                uint32_t bh[4];
                {
                    int kseg = ck * 16 + ks * 2 + (mi & 1);
                    uint32_t bd = bbase0 + (uint32_t)(kseg >> 3) * 128u
                                + (uint32_t)(((kseg & 7) ^ bxor) << 4);
                    ldsm4(bd, bh[0], bh[1], bh[2], bh[3]);
                }
#pragma unroll
                for (int mf = 0; mf < 2; mf++) {
                    mma16816(acc[mf][0], ah[mf], bh[0], bh[1]);
                    mma16816(acc[mf][1], ah[mf], bh[2], bh[3]);
                }
            }
            // poll next group while other warps finish, then one barrier + issue
            if (i + 4 < NCHUNK_H) {
                if (tid == 0) poll_grp(i + 4);
                __syncthreads();
                issue_chunk(i + 4);
            } else if (i + 1 < NCHUNK_H) {
                __syncthreads();             // protect buffer reuse ordering
            }
        }

        // ---- epilogue: xg + bias + LSTM update (c in regs), write h(t+1) ----
        __half* __restrict__ hh_o = g_hh[(t + 1) & 1];
#pragma unroll
        for (int mf = 0; mf < 2; mf++) {
            const int rbase = wm * 32 + mf * 16 + (lid >> 2);
#pragma unroll
            for (int nf = 0; nf < 2; nf++) {
                const int nglob = nb * 8 + wn * 4 + nf * 2 + hcl;
                const float bias0 = g_bs[(hasIF ? 0 : 2) * HH + nglob];
                const float bias1 = g_bs[(hasIF ? 1 : 3) * HH + nglob];
                float d0 = acc[mf][nf][0] + xgv[mf][nf][0].x + bias0;
                float d1 = acc[mf][nf][1] + xgv[mf][nf][0].y + bias1;
                float d2 = acc[mf][nf][2] + xgv[mf][nf][1].x + bias0;
                float d3 = acc[mf][nf][3] + xgv[mf][nf][1].y + bias1;
                float e0 = __shfl_xor_sync(0xFFFFFFFFu, d0, 1);
                float e1 = __shfl_xor_sync(0xFFFFFFFFu, d1, 1);
                float e2 = __shfl_xor_sync(0xFFFFFFFFu, d2, 1);
                float e3 = __shfl_xor_sync(0xFFFFFFFFu, d3, 1);
                if (hasIF) {
#pragma unroll
                    for (int r = 0; r < 2; r++) {
                        float gi = r ? d2 : d0, gf = r ? d3 : d1;
                        float gg = r ? e2 : e0, go = r ? e3 : e1;
                        float iv = 1.f / (1.f + expf(-gi));
                        float fv = 1.f / (1.f + expf(-gf));
                        float gv = tanhf(gg);
                        float ov = 1.f / (1.f + expf(-go));
                        float cn = fv * creg[mf][nf][r] + iv * gv;
                        creg[mf][nf][r] = cn;
                        float hv = ov * tanhf(cn);
                        hh_o[(size_t)(rbase + r * 8) * HH + nglob] = __float2half_rn(hv);
                    }
                }
            }
        }
        __syncthreads();                     // all h stores issued before release
        if (tid == 0) {
            unsigned dummy;
            asm volatile("atom.release.gpu.global.add.u32 %0, [%1], 1;"
                         : "=r"(dummy) : "l"(&g_gc[grp << 5]) : "memory");
        }
    }
}

// ---------------- final FC ------------------------------------------------------
__global__ __launch_bounds__(256) void fc_kernel(
    const float* __restrict__ fcW, const float* __restrict__ fcb, float* __restrict__ out) {
    int w = blockIdx.x * 8 + (threadIdx.x >> 5);
    int lane = threadIdx.x & 31;
    if (w >= BB * CC) return;
    int b = w / CC, c = w - b * CC;
    const __half* __restrict__ hh = g_hh[0] + (size_t)b * HH;   // TT even
    const float* __restrict__ wr = fcW + (size_t)c * HH;
    float s = 0.f;
#pragma unroll 4
    for (int k = lane; k < HH; k += 32)
        s += __half2float(hh[k]) * wr[k];
#pragma unroll
    for (int o = 16; o; o >>= 1) s += __shfl_down_sync(0xFFFFFFFFu, s, o);
    if (lane == 0) out[b * CC + c] = s + fcb[c];
}

extern "C" void kernel_launch(void* const* d_in, const int* in_sizes, int n_in,
                              void* d_out, int out_size) {
    const float* x   = (const float*)d_in[0];
    const float* Wih = (const float*)d_in[1];
    const float* Whh = (const float*)d_in[2];
    const float* bih = (const float*)d_in[3];
    const float* bhh = (const float*)d_in[4];
    const float* fcW = (const float*)d_in[5];
    const float* fcb = (const float*)d_in[6];
    float* out = (float*)d_out;

    cudaFuncSetAttribute(xg_gemm, cudaFuncAttributeMaxDynamicSharedMemorySize, SMEM_PRE);
    cudaFuncSetAttribute(lstm_persist, cudaFuncAttributeMaxDynamicSharedMemorySize, SMEM_DYN);

    prep_w<<<(GG * KTOT + 255) / 256, 256>>>(Wih, Whh);
    prep_x<<<(TT * BB * II + 255) / 256, 256>>>(x);
    prep_misc<<<(BB * HH + 255) / 256, 256>>>(bih, bhh);
    xg_gemm<<<dim3(32, TT, 1), NTHR, SMEM_PRE>>>();
    lstm_persist<<<NCTA, NTHR_P, SMEM_DYN>>>();
    fc_kernel<<<(BB * CC + 7) / 8, 256>>>(fcW, fcb, out);
}

// round 13
// speedup vs baseline: 1.4526x; 1.2056x over previous
#include <cuda_runtime.h>
#include <cuda_fp16.h>
#include <cstdint>
#include <math.h>

#define BB 128
#define TT 512
#define II 256
#define HH 1024
#define GG 4096
#define CC 1000
#define KTOT 1280
#define NCTA 128
#define NTHR 512           // xg_gemm
#define NTHR_P 256         // persistent recurrence
#define NCHUNK_H 8         // h-part K=1024 in 8 chunks of 128

// Persistent kernel SMEM: Whh slice 32x1024 fp16 (2048B rows, resident)
//   + per-warp A pipelines: 8 warps x 4 buffers x 4KB = 128 KB
#define W_HI 0u
#define A_BUF 65536u
#define SMEM_DYN (65536 + 131072 + 256)

// Precompute kernel SMEM: B 64K | A_hi 64K | A_lo 64K
#define PRE_B  0u
#define PRE_AH 65536u
#define PRE_AL 131072u
#define SMEM_PRE (196608 + 256)

// ---------------- device globals (no dynamic alloc) ---------------------------
__device__ __align__(16) __half g_Wh[GG * KTOT];            // weights fp16, permuted
__device__ __align__(16) __half g_xh[TT * BB * II];         // x hi, [t][m][k]
__device__ __align__(16) __half g_xl[TT * BB * II];         // x lo
__device__ __align__(16) __half g_hh[2][BB * HH];           // h fp16 ping-pong
__device__ float g_bs[GG];
__device__ float g_xg[268435456];                           // [t][nb][m][32] = 1 GB
__device__ unsigned g_gc[8 * 32];                           // counters, 128B apart

// ---------------- helpers ------------------------------------------------------
__device__ __forceinline__ uint32_t smem_u32(const void* p) {
    uint32_t a;
    asm("{ .reg .u64 t; cvta.to.shared.u64 t, %1; cvt.u32.u64 %0, t; }" : "=r"(a) : "l"(p));
    return a;
}
__device__ __forceinline__ void cp16(uint32_t saddr, const void* gaddr) {
    asm volatile("cp.async.cg.shared.global [%0], [%1], 16;" :: "r"(saddr), "l"(gaddr) : "memory");
}
__device__ __forceinline__ void ldsm4(uint32_t addr, uint32_t& r0, uint32_t& r1,
                                      uint32_t& r2, uint32_t& r3) {
    asm volatile("ldmatrix.sync.aligned.m8n8.x4.shared.b16 {%0,%1,%2,%3}, [%4];"
                 : "=r"(r0), "=r"(r1), "=r"(r2), "=r"(r3) : "r"(addr));
}
__device__ __forceinline__ void mma16816(float* c, const uint32_t* a, uint32_t b0, uint32_t b1) {
    asm volatile(
        "mma.sync.aligned.m16n8k16.row.col.f32.f16.f16.f32 "
        "{%0,%1,%2,%3}, {%4,%5,%6,%7}, {%8,%9}, {%0,%1,%2,%3};"
        : "+f"(c[0]), "+f"(c[1]), "+f"(c[2]), "+f"(c[3])
        : "r"(a[0]), "r"(a[1]), "r"(a[2]), "r"(a[3]), "r"(b0), "r"(b1));
}

// ---------------- prep kernels -------------------------------------------------
// Stored row r = nb*32 + hc*4 + q  <->  original row q*H + nb*8 + hc.
__global__ void prep_w(const float* __restrict__ Wih, const float* __restrict__ Whh) {
    int idx = blockIdx.x * blockDim.x + threadIdx.x;
    if (idx >= GG * KTOT) return;
    int r = idx / KTOT, k = idx - r * KTOT;
    int nb = r >> 5, j = r & 31, hc = j >> 2, q = j & 3;
    int orig = q * HH + nb * 8 + hc;
    float v = (k < II) ? Wih[(size_t)orig * II + k] : Whh[(size_t)orig * HH + (k - II)];
    g_Wh[idx] = __float2half_rn(v);
}

__global__ void prep_x(const float* __restrict__ x) {
    int idx = blockIdx.x * blockDim.x + threadIdx.x;
    if (idx >= TT * BB * II) return;
    int t = idx / (BB * II);
    int rem = idx - t * (BB * II);
    int m = rem / II, k = rem - m * II;
    float v = x[((size_t)m * TT + t) * II + k];
    __half hi = __float2half_rn(v);
    g_xh[idx] = hi;
    g_xl[idx] = __float2half_rn(v - __half2float(hi));
}

__global__ void prep_misc(const float* __restrict__ bih, const float* __restrict__ bhh) {
    int i = blockIdx.x * blockDim.x + threadIdx.x;
    if (i < BB * HH) g_hh[0][i] = __float2half_rn(0.f);
    if (i < GG) g_bs[i] = bih[i] + bhh[i];
    if (i < 8 * 32) g_gc[i] = 0u;
}

// ---------------- xg precompute: xg[t] = (xhi+xlo) @ Wih_perm^T -----------------
__global__ __launch_bounds__(NTHR, 1) void xg_gemm() {
    extern __shared__ __align__(16) char dsm_raw[];
    const uint32_t dbase = (smem_u32(dsm_raw) + 127) & ~127u;

    const int tid = threadIdx.x;
    const int wid = tid >> 5, lid = tid & 31;
    const int wm = wid >> 1, wn = wid & 1;
    const int nt = blockIdx.x;      // 128-col gate tile
    const int t  = blockIdx.y;
    const int mi = lid >> 3, lr = lid & 7;

    const __half* __restrict__ xsh = g_xh + (size_t)t * (BB * II);
    const __half* __restrict__ xsl = g_xl + (size_t)t * (BB * II);

#pragma unroll
    for (int s = 0; s < 8; s++) {
        int idx = tid + NTHR * s;           // 0..4095
        int row = idx >> 5, seg = idx & 31;
        uint32_t so = (uint32_t)(seg >> 3) * 16384u + (uint32_t)row * 128u
                    + (uint32_t)(((seg & 7) ^ (row & 7)) << 4);
        cp16(dbase + PRE_B + so, g_Wh + (size_t)(nt * 128 + row) * KTOT + seg * 8);
        cp16(dbase + PRE_AH + so, xsh + (size_t)row * II + seg * 8);
        cp16(dbase + PRE_AL + so, xsl + (size_t)row * II + seg * 8);
    }
    asm volatile("cp.async.commit_group;" ::: "memory");
    asm volatile("cp.async.wait_group 0;" ::: "memory");
    __syncthreads();

    float acc[8][4];
#pragma unroll
    for (int j = 0; j < 8; j++)
#pragma unroll
        for (int i = 0; i < 4; i++) acc[j][i] = 0.f;

    const int arow = wm * 16 + ((mi & 1) << 3) + lr;
    const int axor = arow & 7;

#pragma unroll
    for (int ks = 0; ks < 16; ks++) {
        uint32_t ah[4], al[4];
        {
            int ksega = (ks & 3) * 2 + (mi >> 1);
            uint32_t ad = dbase + PRE_AH + (uint32_t)(ks >> 2) * 16384u
                        + (uint32_t)arow * 128u + (uint32_t)((ksega ^ axor) << 4);
            ldsm4(ad, ah[0], ah[1], ah[2], ah[3]);
            ldsm4(ad + (PRE_AL - PRE_AH), al[0], al[1], al[2], al[3]);
        }
#pragma unroll
        for (int g = 0; g < 4; g++) {
            int brow = wn * 64 + g * 16 + ((mi >> 1) << 3) + lr;
            int ksegb = (ks & 3) * 2 + (mi & 1);
            uint32_t bd = dbase + PRE_B + (uint32_t)(ks >> 2) * 16384u
                        + (uint32_t)brow * 128u + (uint32_t)((ksegb ^ (brow & 7)) << 4);
            uint32_t bh[4];
            ldsm4(bd, bh[0], bh[1], bh[2], bh[3]);
            mma16816(acc[g * 2 + 0], ah, bh[0], bh[1]);
            mma16816(acc[g * 2 + 1], ah, bh[2], bh[3]);
            mma16816(acc[g * 2 + 0], al, bh[0], bh[1]);
            mma16816(acc[g * 2 + 1], al, bh[2], bh[3]);
        }
    }

    const int lq = lid & 3;
#pragma unroll
    for (int j = 0; j < 8; j++) {
        int c = wn * 64 + (j >> 1) * 16 + (j & 1) * 8 + lq * 2;
        int C = nt * 128 + c;
        int nbv = C >> 5, c31 = C & 31;
#pragma unroll
        for (int r = 0; r < 2; r++) {
            int m = wm * 16 + (lid >> 2) + r * 8;
            size_t idx = (((size_t)t * NCTA + nbv) * 128 + m) * 32 + c31;
            *reinterpret_cast<float2*>(g_xg + idx) =
                make_float2(acc[j][r * 2], acc[j][r * 2 + 1]);
        }
    }
}

// ---------------- persistent LSTM recurrence -----------------------------------
// 128 CTAs x 256 thr = 8 warps, arrangement 8m x 1n (warp tile 16x32).
// Each warp owns 16 batch rows exclusively: private A buffers (4-deep), private
// cp.async pipeline, ZERO intra-CTA barriers in the chunk loop. One CTA barrier
// per step (epilogue) before the group-release atomic. c-state in registers.
__global__ __launch_bounds__(NTHR_P, 1) void lstm_persist() {
    extern __shared__ __align__(16) char dsm_raw[];
    const uint32_t dbase = (smem_u32(dsm_raw) + 127) & ~127u;

    const int tid = threadIdx.x;
    const int wid = tid >> 5, lid = tid & 31;
    const int nb = blockIdx.x;
    const int grp = nb >> 4;                 // producer group 0..7
    const int mi = lid >> 3, lr = lid & 7;

    // ---- load Whh slice (32 rows x k 256..1280) into SMEM once ----
#pragma unroll
    for (int s = 0; s < 16; s++) {
        int idx = tid + NTHR_P * s;          // 0..4095
        int row = idx >> 7, kseg = idx & 127;
        size_t go = (size_t)(nb * 32 + row) * KTOT + II + kseg * 8;
        uint32_t so = (uint32_t)row * 2048u + (uint32_t)(kseg >> 3) * 128u
                    + (uint32_t)(((kseg & 7) ^ (row & 7)) << 4);
        cp16(dbase + W_HI + so, g_Wh + go);
    }
    asm volatile("cp.async.commit_group;" ::: "memory");
    asm volatile("cp.async.wait_group 0;" ::: "memory");
    __syncthreads();

    const int lq = lid & 3;
    const bool hasIF = (lq & 1) == 0;
    const int hcl = lq >> 1;

    // per-warp A staging: base + 4 buffers x 4KB
    const uint32_t wabase = dbase + A_BUF + (uint32_t)wid * 16384u;
    const int arl = ((mi & 1) << 3) + lr;    // A local row for ldsm (0..15)
    const uint32_t aoff = (uint32_t)arl * 128u;
    const int axor = arl & 7;

    float creg[4][2];
#pragma unroll
    for (int a = 0; a < 4; a++) { creg[a][0] = 0.f; creg[a][1] = 0.f; }

#pragma unroll 1
    for (int t = 0; t < TT; t++) {
        const __half* __restrict__ hsh = g_hh[t & 1];
        const unsigned need = 16u * (unsigned)t;

        // xg prefetch (independent; consumed at epilogue)
        float2 xgv[4][2];
        {
            const float* xb = g_xg + (((size_t)t * NCTA + nb) * 128) * 32;
            const int r0 = wid * 16 + (lid >> 2);
            const int c0 = lq * 2;
#pragma unroll
            for (int nf = 0; nf < 4; nf++)
#pragma unroll
                for (int r = 0; r < 2; r++)
                    xgv[nf][r] = *reinterpret_cast<const float2*>(
                        xb + (size_t)(r0 + r * 8) * 32 + c0 + nf * 8);
        }

        auto poll = [&](int i) {             // warp-collective (same addr, 1 req)
            const int ck = (grp + i) & 7;
            unsigned v;
            asm volatile("ld.acquire.gpu.global.u32 %0, [%1];"
                         : "=r"(v) : "l"(&g_gc[ck << 5]) : "memory");
            while (v < need) {
                __nanosleep(32);
                asm volatile("ld.acquire.gpu.global.u32 %0, [%1];"
                             : "=r"(v) : "l"(&g_gc[ck << 5]) : "memory");
            }
        };
        auto issue = [&](int i) {            // warp loads its own 16 rows (4 KB)
            const int ck = (grp + i) & 7;
            const uint32_t bofs = wabase + (uint32_t)(i & 3) * 4096u;
#pragma unroll
            for (int s = 0; s < 8; s++) {
                int idx = lid + 32 * s;      // 0..255
                int r = idx >> 4, seg = idx & 15;
                uint32_t sa = bofs + (uint32_t)(seg >> 3) * 2048u
                            + (uint32_t)r * 128u
                            + (uint32_t)(((seg & 7) ^ (r & 7)) << 4);
                cp16(sa, hsh + (size_t)(wid * 16 + r) * HH + ck * 128 + seg * 8);
            }
            asm volatile("cp.async.commit_group;" ::: "memory");
        };

        float acc[4][4];
#pragma unroll
        for (int a = 0; a < 4; a++)
#pragma unroll
            for (int i = 0; i < 4; i++) acc[a][i] = 0.f;

        poll(0); issue(0);
        poll(1); issue(1);
        poll(2); issue(2);
        poll(3); issue(3);

#pragma unroll 1
        for (int i = 0; i < NCHUNK_H; i++) {
            {
                int pend = NCHUNK_H - 1 - i; if (pend > 3) pend = 3;
                if (pend == 3)      asm volatile("cp.async.wait_group 3;" ::: "memory");
                else if (pend == 2) asm volatile("cp.async.wait_group 2;" ::: "memory");
                else if (pend == 1) asm volatile("cp.async.wait_group 1;" ::: "memory");
                else                asm volatile("cp.async.wait_group 0;" ::: "memory");
            }
            const int ck = (grp + i) & 7;
            const uint32_t abase = wabase + (uint32_t)(i & 3) * 4096u;

#pragma unroll
            for (int ks = 0; ks < 8; ks++) {
                uint32_t ah[4];
                {
                    int ksega = (ks & 3) * 2 + (mi >> 1);
                    uint32_t ad = abase + (uint32_t)(ks >> 2) * 2048u + aoff
                                + (uint32_t)((ksega ^ axor) << 4);
                    ldsm4(ad, ah[0], ah[1], ah[2], ah[3]);
                }
                const int kseg = ck * 16 + ks * 2 + (mi & 1);
#pragma unroll
                for (int g = 0; g < 2; g++) {
                    int brow = g * 16 + ((mi >> 1) << 3) + lr;
                    uint32_t bd = dbase + W_HI + (uint32_t)brow * 2048u
                                + (uint32_t)(kseg >> 3) * 128u
                                + (uint32_t)(((kseg & 7) ^ (brow & 7)) << 4);
                    uint32_t bh[4];
                    ldsm4(bd, bh[0], bh[1], bh[2], bh[3]);
                    mma16816(acc[g * 2 + 0], ah, bh[0], bh[1]);
                    mma16816(acc[g * 2 + 1], ah, bh[2], bh[3]);
                }
            }
            if (i + 4 < NCHUNK_H) { poll(i + 4); issue(i + 4); }
        }

        // ---- epilogue: xg + bias + LSTM update (c in regs), write h(t+1) ----
        __half* __restrict__ hh_o = g_hh[(t + 1) & 1];
        const int rbase = wid * 16 + (lid >> 2);
#pragma unroll
        for (int nf = 0; nf < 4; nf++) {
            const int nglob = nb * 8 + nf * 2 + hcl;
            const float bias0 = g_bs[(hasIF ? 0 : 2) * HH + nglob];
            const float bias1 = g_bs[(hasIF ? 1 : 3) * HH + nglob];
            float d0 = acc[nf][0] + xgv[nf][0].x + bias0;
            float d1 = acc[nf][1] + xgv[nf][0].y + bias1;
            float d2 = acc[nf][2] + xgv[nf][1].x + bias0;
            float d3 = acc[nf][3] + xgv[nf][1].y + bias1;
            float e0 = __shfl_xor_sync(0xFFFFFFFFu, d0, 1);
            float e1 = __shfl_xor_sync(0xFFFFFFFFu, d1, 1);
            float e2 = __shfl_xor_sync(0xFFFFFFFFu, d2, 1);
            float e3 = __shfl_xor_sync(0xFFFFFFFFu, d3, 1);
            if (hasIF) {
#pragma unroll
                for (int r = 0; r < 2; r++) {
                    float gi = r ? d2 : d0, gf = r ? d3 : d1;
                    float gg = r ? e2 : e0, go = r ? e3 : e1;
                    float iv = 1.f / (1.f + expf(-gi));
                    float fv = 1.f / (1.f + expf(-gf));
                    float gv = tanhf(gg);
                    float ov = 1.f / (1.f + expf(-go));
                    float cn = fv * creg[nf][r] + iv * gv;
                    creg[nf][r] = cn;
                    float hv = ov * tanhf(cn);
                    hh_o[(size_t)(rbase + r * 8) * HH + nglob] = __float2half_rn(hv);
                }
            }
        }
        __syncthreads();                     // all warps' h stores before release
        if (tid == 0) {
            unsigned dummy;
            asm volatile("atom.release.gpu.global.add.u32 %0, [%1], 1;"
                         : "=r"(dummy) : "l"(&g_gc[grp << 5]) : "memory");
        }
    }
}

// ---------------- final FC ------------------------------------------------------
__global__ __launch_bounds__(256) void fc_kernel(
    const float* __restrict__ fcW, const float* __restrict__ fcb, float* __restrict__ out) {
    int w = blockIdx.x * 8 + (threadIdx.x >> 5);
    int lane = threadIdx.x & 31;
    if (w >= BB * CC) return;
    int b = w / CC, c = w - b * CC;
    const __half* __restrict__ hh = g_hh[0] + (size_t)b * HH;   // TT even
    const float* __restrict__ wr = fcW + (size_t)c * HH;
    float s = 0.f;
#pragma unroll 4
    for (int k = lane; k < HH; k += 32)
        s += __half2float(hh[k]) * wr[k];
#pragma unroll
    for (int o = 16; o; o >>= 1) s += __shfl_down_sync(0xFFFFFFFFu, s, o);
    if (lane == 0) out[b * CC + c] = s + fcb[c];
}

extern "C" void kernel_launch(void* const* d_in, const int* in_sizes, int n_in,
                              void* d_out, int out_size) {
    const float* x   = (const float*)d_in[0];
    const float* Wih = (const float*)d_in[1];
    const float* Whh = (const float*)d_in[2];
    const float* bih = (const float*)d_in[3];
    const float* bhh = (const float*)d_in[4];
    const float* fcW = (const float*)d_in[5];
    const float* fcb = (const float*)d_in[6];
    float* out = (float*)d_out;

    cudaFuncSetAttribute(xg_gemm, cudaFuncAttributeMaxDynamicSharedMemorySize, SMEM_PRE);
    cudaFuncSetAttribute(lstm_persist, cudaFuncAttributeMaxDynamicSharedMemorySize, SMEM_DYN);

    prep_w<<<(GG * KTOT + 255) / 256, 256>>>(Wih, Whh);
    prep_x<<<(TT * BB * II + 255) / 256, 256>>>(x);
    prep_misc<<<(BB * HH + 255) / 256, 256>>>(bih, bhh);
    xg_gemm<<<dim3(32, TT, 1), NTHR, SMEM_PRE>>>();
    lstm_persist<<<NCTA, NTHR_P, SMEM_DYN>>>();
    fc_kernel<<<(BB * CC + 7) / 8, 256>>>(fcW, fcb, out);
}